// round 9
// baseline (speedup 1.0000x reference)
#include <cuda_runtime.h>

// SparseBlock: submanifold sparse conv (9-tap gathered GEMM) + BatchNorm(train) + LeakyReLU(0.333)
// Inputs (metadata order): feats [N,128] f32, W [9,128,128] f32, bias[128], gamma[128], beta[128],
//                          neigh_idx [N,9] int32 (sentinel value == N -> zero row)
// Output: [N,128] f32.

#define CIN   128
#define COUT  128
#define KTAPS 9
#define BM    64
#define BK    32
#define STATS_BLOCKS 1024
#define EPS_BN  1e-4f
#define LEAK    0.333f

typedef unsigned long long u64;

__device__ __forceinline__ u64 pack2(float lo, float hi) {
    u64 r;
    asm("mov.b64 %0, {%1, %2};" : "=l"(r) : "f"(lo), "f"(hi));
    return r;
}
__device__ __forceinline__ float2 unpack2(u64 v) {
    float2 r;
    asm("mov.b64 {%0, %1}, %2;" : "=f"(r.x), "=f"(r.y) : "l"(v));
    return r;
}
// Packed dual-FMA: d.lo += a.lo*b.lo ; d.hi += a.hi*b.hi  (FFMA2 — only reachable via PTX)
__device__ __forceinline__ void fma2(u64& d, u64 a, u64 b) {
    asm("fma.rn.f32x2 %0, %1, %2, %0;" : "+l"(d) : "l"(a), "l"(b));
}

// Deterministic-reduction scratch (no device-side allocation allowed).
__device__ float g_psum[STATS_BLOCKS * COUT];
__device__ float g_psumsq[STATS_BLOCKS * COUT];
__device__ float g_scale[COUT];
__device__ float g_shift[COUT];

// ---------------------------------------------------------------------------
// Phase A: gathered GEMM.  Tile: 64 rows x 128 cols, K = 9*128 (taps x Cin).
// 128 threads, each computing an 8x(4+4) micro-tile held as packed f32x2 pairs.
// ---------------------------------------------------------------------------
__global__ __launch_bounds__(128, 3)
void conv_kernel(const float* __restrict__ feats, const float* __restrict__ W,
                 const float* __restrict__ bias, const int* __restrict__ neigh,
                 float* __restrict__ out, int N)
{
    // As padded to 36 floats/row: 16B-aligned rows, conflict-free float4 stores.
    __shared__ __align__(16) float As[BM][36];
    __shared__ __align__(16) float Bs[BK][COUT];
    __shared__ int sNeigh[BM];

    const int t  = threadIdx.x;
    const int tr = t >> 4;          // 0..7  -> row group
    const int tc = t & 15;          // 0..15 -> col group
    const int r0 = tr * 8;
    const int c0 = tc * 4;          // first 4-col slab
    const int c1 = 64 + tc * 4;     // second 4-col slab (split avoids LDS conflicts)
    const int m0 = blockIdx.x * BM;

    u64 acc[8][4];
    {
        float4 b0 = *(const float4*)(bias + c0);
        float4 b1 = *(const float4*)(bias + c1);
        u64 i0 = pack2(b0.x, b0.y), i1 = pack2(b0.z, b0.w);
        u64 i2 = pack2(b1.x, b1.y), i3 = pack2(b1.z, b1.w);
        #pragma unroll
        for (int r = 0; r < 8; ++r) {
            acc[r][0] = i0; acc[r][1] = i1; acc[r][2] = i2; acc[r][3] = i3;
        }
    }

    for (int k = 0; k < KTAPS; ++k) {
        __syncthreads();                       // previous chunk's compute done
        if (t < BM) {
            int gr = m0 + t;
            sNeigh[t] = (gr < N) ? neigh[gr * KTAPS + k] : N;
        }
        __syncthreads();

        #pragma unroll
        for (int kc = 0; kc < CIN / BK; ++kc) {
            // ---- gather A chunk: 64 rows x 32 floats (float4 granularity) ----
            #pragma unroll
            for (int i = 0; i < 4; ++i) {
                int idx  = t + i * 128;        // 0..511
                int row  = idx >> 3;
                int quad = idx & 7;
                int nb   = sNeigh[row];
                float4 v = make_float4(0.f, 0.f, 0.f, 0.f);
                if (nb < N)
                    v = *(const float4*)(feats + (size_t)nb * CIN + kc * BK + quad * 4);
                *(float4*)(&As[row][quad * 4]) = v;
            }
            // ---- stage B chunk: W[k][kc*32 .. +32][0..128] ----
            const float* Wk = W + ((size_t)k * CIN + kc * BK) * COUT;
            #pragma unroll
            for (int i = 0; i < 8; ++i) {
                int idx = t + i * 128;         // 0..1023
                int row = idx >> 5;
                int q   = idx & 31;
                *(float4*)(&Bs[row][q * 4]) = *(const float4*)(Wk + row * COUT + q * 4);
            }
            __syncthreads();

            // ---- 32 k-steps, a-operand vectorized 4 at a time ----
            #pragma unroll
            for (int kk4 = 0; kk4 < BK; kk4 += 4) {
                float4 av[8];
                #pragma unroll
                for (int r = 0; r < 8; ++r)
                    av[r] = *(const float4*)(&As[r0 + r][kk4]);
                #pragma unroll
                for (int j = 0; j < 4; ++j) {
                    float4 b0 = *(const float4*)(&Bs[kk4 + j][c0]);
                    float4 b1 = *(const float4*)(&Bs[kk4 + j][c1]);
                    u64 bp0 = pack2(b0.x, b0.y), bp1 = pack2(b0.z, b0.w);
                    u64 bp2 = pack2(b1.x, b1.y), bp3 = pack2(b1.z, b1.w);
                    #pragma unroll
                    for (int r = 0; r < 8; ++r) {
                        float a = (j == 0) ? av[r].x : (j == 1) ? av[r].y
                                : (j == 2) ? av[r].z : av[r].w;
                        u64 aa = pack2(a, a);
                        fma2(acc[r][0], aa, bp0);
                        fma2(acc[r][1], aa, bp1);
                        fma2(acc[r][2], aa, bp2);
                        fma2(acc[r][3], aa, bp3);
                    }
                }
            }
            __syncthreads();
        }
    }

    // ---- epilogue: pre-BN conv output ----
    #pragma unroll
    for (int r = 0; r < 8; ++r) {
        int gr = m0 + r0 + r;
        if (gr < N) {
            float2 p0 = unpack2(acc[r][0]);
            float2 p1 = unpack2(acc[r][1]);
            float2 p2 = unpack2(acc[r][2]);
            float2 p3 = unpack2(acc[r][3]);
            *(float4*)(out + (size_t)gr * COUT + c0) = make_float4(p0.x, p0.y, p1.x, p1.y);
            *(float4*)(out + (size_t)gr * COUT + c1) = make_float4(p2.x, p2.y, p3.x, p3.y);
        }
    }
}

// ---------------------------------------------------------------------------
// Phase B1: per-block partial sums / sumsq per channel (deterministic order).
// ---------------------------------------------------------------------------
__global__ void stats_partial(const float* __restrict__ out, int N)
{
    const int c = threadIdx.x;                 // 128 threads = 128 channels
    float s = 0.f, s2 = 0.f;
    for (int r = blockIdx.x; r < N; r += gridDim.x) {
        float v = out[(size_t)r * COUT + c];
        s  += v;
        s2 += v * v;
    }
    g_psum  [blockIdx.x * COUT + c] = s;
    g_psumsq[blockIdx.x * COUT + c] = s2;
}

// ---------------------------------------------------------------------------
// Phase B2: final reduce -> scale/shift per channel.
// ---------------------------------------------------------------------------
__global__ void stats_final(const float* __restrict__ gamma,
                            const float* __restrict__ beta, int N)
{
    const int c = threadIdx.x;
    float s = 0.f, s2 = 0.f;
    for (int i = 0; i < STATS_BLOCKS; ++i) {
        s  += g_psum  [i * COUT + c];
        s2 += g_psumsq[i * COUT + c];
    }
    float invN = 1.f / (float)N;
    float mean = s * invN;
    float var  = s2 * invN - mean * mean;      // population variance (ddof=0)
    float rstd = rsqrtf(var + EPS_BN);
    float sc   = gamma[c] * rstd;
    g_scale[c] = sc;
    g_shift[c] = beta[c] - mean * sc;
}

// ---------------------------------------------------------------------------
// Phase C: in-place BN affine + LeakyReLU, float4 vectorized.
// ---------------------------------------------------------------------------
__global__ void bn_lrelu(float* __restrict__ out, int N)
{
    const size_t total4 = (size_t)N * (COUT / 4);
    float4* o4 = (float4*)out;
    for (size_t i = (size_t)blockIdx.x * blockDim.x + threadIdx.x;
         i < total4; i += (size_t)gridDim.x * blockDim.x) {
        float4 v = o4[i];
        int cb = (int)((i & (COUT / 4 - 1)) * 4);   // channel base, multiple of 4
        float4 sc = *(const float4*)(g_scale + cb);
        float4 sh = *(const float4*)(g_shift + cb);
        float y;
        y = v.x * sc.x + sh.x; v.x = (y > 0.f) ? y : LEAK * y;
        y = v.y * sc.y + sh.y; v.y = (y > 0.f) ? y : LEAK * y;
        y = v.z * sc.z + sh.z; v.z = (y > 0.f) ? y : LEAK * y;
        y = v.w * sc.w + sh.w; v.w = (y > 0.f) ? y : LEAK * y;
        o4[i] = v;
    }
}

// ---------------------------------------------------------------------------
extern "C" void kernel_launch(void* const* d_in, const int* in_sizes, int n_in,
                              void* d_out, int out_size)
{
    const float* feats = (const float*)d_in[0];
    const float* W     = (const float*)d_in[1];
    const float* bias  = (const float*)d_in[2];
    const float* gamma = (const float*)d_in[3];
    const float* beta  = (const float*)d_in[4];
    const int*   neigh = (const int*)  d_in[5];
    float* out = (float*)d_out;

    const int N = in_sizes[0] / CIN;
    const int mblocks = (N + BM - 1) / BM;

    conv_kernel  <<<mblocks, 128>>>(feats, W, bias, neigh, out, N);
    stats_partial<<<STATS_BLOCKS, COUT>>>(out, N);
    stats_final  <<<1, COUT>>>(gamma, beta, N);
    bn_lrelu     <<<2048, 256>>>(out, N);
}

// round 10
// speedup vs baseline: 1.5575x; 1.5575x over previous
#include <cuda_runtime.h>

// SparseBlock: submanifold sparse conv (9-tap gathered GEMM) + BatchNorm(train) + LeakyReLU(0.333)
// Inputs (metadata order): feats [N,128] f32, W [9,128,128] f32, bias[128], gamma[128], beta[128],
//                          neigh_idx [N,9] int32 (sentinel value == N -> zero row)
// Output: [N,128] f32.

#define CIN   128
#define COUT  128
#define KTAPS 9
#define BM    64
#define BK    32
#define STATS_BLOCKS 1024
#define EPS_BN  1e-4f
#define LEAK    0.333f

typedef unsigned long long u64;

__device__ __forceinline__ u64 pack2(float lo, float hi) {
    u64 r;
    asm("mov.b64 %0, {%1, %2};" : "=l"(r) : "f"(lo), "f"(hi));
    return r;
}
__device__ __forceinline__ float2 unpack2(u64 v) {
    float2 r;
    asm("mov.b64 {%0, %1}, %2;" : "=f"(r.x), "=f"(r.y) : "l"(v));
    return r;
}
// Packed dual-FMA: d.lo += a.lo*b.lo ; d.hi += a.hi*b.hi  (FFMA2 — only reachable via PTX)
__device__ __forceinline__ void fma2(u64& d, u64 a, u64 b) {
    asm("fma.rn.f32x2 %0, %1, %2, %0;" : "+l"(d) : "l"(a), "l"(b));
}

// Deterministic-reduction scratch (no device-side allocation allowed).
__device__ float g_psum[STATS_BLOCKS * COUT];
__device__ float g_psumsq[STATS_BLOCKS * COUT];
__device__ float g_scale[COUT];
__device__ float g_shift[COUT];

// ---------------------------------------------------------------------------
// Phase A: gathered GEMM.  Tile: 64 rows x 128 cols, K = 9*128 (taps x Cin).
// 128 threads, each computing an 8x(4+4) micro-tile held as packed f32x2 pairs.
// ---------------------------------------------------------------------------
__global__ __launch_bounds__(128, 3)
void conv_kernel(const float* __restrict__ feats, const float* __restrict__ W,
                 const float* __restrict__ bias, const int* __restrict__ neigh,
                 float* __restrict__ out, int N)
{
    // As padded to 36 floats/row: 16B-aligned rows, conflict-free float4 stores.
    __shared__ __align__(16) float As[BM][36];
    __shared__ __align__(16) float Bs[BK][COUT];
    __shared__ int sNeigh[BM];

    const int t  = threadIdx.x;
    const int tr = t >> 4;          // 0..7  -> row group
    const int tc = t & 15;          // 0..15 -> col group
    const int r0 = tr * 8;
    const int c0 = tc * 4;          // first 4-col slab
    const int c1 = 64 + tc * 4;     // second 4-col slab (split avoids LDS conflicts)
    const int m0 = blockIdx.x * BM;

    u64 acc[8][4];
    {
        float4 b0 = *(const float4*)(bias + c0);
        float4 b1 = *(const float4*)(bias + c1);
        u64 i0 = pack2(b0.x, b0.y), i1 = pack2(b0.z, b0.w);
        u64 i2 = pack2(b1.x, b1.y), i3 = pack2(b1.z, b1.w);
        #pragma unroll
        for (int r = 0; r < 8; ++r) {
            acc[r][0] = i0; acc[r][1] = i1; acc[r][2] = i2; acc[r][3] = i3;
        }
    }

    for (int k = 0; k < KTAPS; ++k) {
        __syncthreads();                       // previous chunk's compute done
        if (t < BM) {
            int gr = m0 + t;
            sNeigh[t] = (gr < N) ? neigh[gr * KTAPS + k] : N;
        }
        __syncthreads();

        #pragma unroll
        for (int kc = 0; kc < CIN / BK; ++kc) {
            // ---- gather A chunk: 64 rows x 32 floats (float4 granularity) ----
            #pragma unroll
            for (int i = 0; i < 4; ++i) {
                int idx  = t + i * 128;        // 0..511
                int row  = idx >> 3;
                int quad = idx & 7;
                int nb   = sNeigh[row];
                float4 v = make_float4(0.f, 0.f, 0.f, 0.f);
                if (nb < N)
                    v = *(const float4*)(feats + (size_t)nb * CIN + kc * BK + quad * 4);
                *(float4*)(&As[row][quad * 4]) = v;
            }
            // ---- stage B chunk: W[k][kc*32 .. +32][0..128] ----
            const float* Wk = W + ((size_t)k * CIN + kc * BK) * COUT;
            #pragma unroll
            for (int i = 0; i < 8; ++i) {
                int idx = t + i * 128;         // 0..1023
                int row = idx >> 5;
                int q   = idx & 31;
                *(float4*)(&Bs[row][q * 4]) = *(const float4*)(Wk + row * COUT + q * 4);
            }
            __syncthreads();

            // ---- 32 k-steps, a-operand vectorized 4 at a time ----
            #pragma unroll
            for (int kk4 = 0; kk4 < BK; kk4 += 4) {
                float4 av[8];
                #pragma unroll
                for (int r = 0; r < 8; ++r)
                    av[r] = *(const float4*)(&As[r0 + r][kk4]);
                #pragma unroll
                for (int j = 0; j < 4; ++j) {
                    float4 b0 = *(const float4*)(&Bs[kk4 + j][c0]);
                    float4 b1 = *(const float4*)(&Bs[kk4 + j][c1]);
                    u64 bp0 = pack2(b0.x, b0.y), bp1 = pack2(b0.z, b0.w);
                    u64 bp2 = pack2(b1.x, b1.y), bp3 = pack2(b1.z, b1.w);
                    #pragma unroll
                    for (int r = 0; r < 8; ++r) {
                        float a = (j == 0) ? av[r].x : (j == 1) ? av[r].y
                                : (j == 2) ? av[r].z : av[r].w;
                        u64 aa = pack2(a, a);
                        fma2(acc[r][0], aa, bp0);
                        fma2(acc[r][1], aa, bp1);
                        fma2(acc[r][2], aa, bp2);
                        fma2(acc[r][3], aa, bp3);
                    }
                }
            }
            __syncthreads();
        }
    }

    // ---- epilogue: pre-BN conv output ----
    #pragma unroll
    for (int r = 0; r < 8; ++r) {
        int gr = m0 + r0 + r;
        if (gr < N) {
            float2 p0 = unpack2(acc[r][0]);
            float2 p1 = unpack2(acc[r][1]);
            float2 p2 = unpack2(acc[r][2]);
            float2 p3 = unpack2(acc[r][3]);
            *(float4*)(out + (size_t)gr * COUT + c0) = make_float4(p0.x, p0.y, p1.x, p1.y);
            *(float4*)(out + (size_t)gr * COUT + c1) = make_float4(p2.x, p2.y, p3.x, p3.y);
        }
    }
}

// ---------------------------------------------------------------------------
// Phase B1: per-block partial sums / sumsq per channel (deterministic order).
// ---------------------------------------------------------------------------
__global__ void stats_partial(const float* __restrict__ out, int N)
{
    const int c = threadIdx.x;                 // 128 threads = 128 channels
    float s = 0.f, s2 = 0.f;
    for (int r = blockIdx.x; r < N; r += gridDim.x) {
        float v = out[(size_t)r * COUT + c];
        s  += v;
        s2 += v * v;
    }
    g_psum  [blockIdx.x * COUT + c] = s;
    g_psumsq[blockIdx.x * COUT + c] = s2;
}

// ---------------------------------------------------------------------------
// Phase B2: final reduce -> scale/shift per channel.
// ---------------------------------------------------------------------------
__global__ void stats_final(const float* __restrict__ gamma,
                            const float* __restrict__ beta, int N)
{
    const int c = threadIdx.x;
    float s = 0.f, s2 = 0.f;
    for (int i = 0; i < STATS_BLOCKS; ++i) {
        s  += g_psum  [i * COUT + c];
        s2 += g_psumsq[i * COUT + c];
    }
    float invN = 1.f / (float)N;
    float mean = s * invN;
    float var  = s2 * invN - mean * mean;      // population variance (ddof=0)
    float rstd = rsqrtf(var + EPS_BN);
    float sc   = gamma[c] * rstd;
    g_scale[c] = sc;
    g_shift[c] = beta[c] - mean * sc;
}

// ---------------------------------------------------------------------------
// Phase C: in-place BN affine + LeakyReLU, float4 vectorized.
// ---------------------------------------------------------------------------
__global__ void bn_lrelu(float* __restrict__ out, int N)
{
    const size_t total4 = (size_t)N * (COUT / 4);
    float4* o4 = (float4*)out;
    for (size_t i = (size_t)blockIdx.x * blockDim.x + threadIdx.x;
         i < total4; i += (size_t)gridDim.x * blockDim.x) {
        float4 v = o4[i];
        int cb = (int)((i & (COUT / 4 - 1)) * 4);   // channel base, multiple of 4
        float4 sc = *(const float4*)(g_scale + cb);
        float4 sh = *(const float4*)(g_shift + cb);
        float y;
        y = v.x * sc.x + sh.x; v.x = (y > 0.f) ? y : LEAK * y;
        y = v.y * sc.y + sh.y; v.y = (y > 0.f) ? y : LEAK * y;
        y = v.z * sc.z + sh.z; v.z = (y > 0.f) ? y : LEAK * y;
        y = v.w * sc.w + sh.w; v.w = (y > 0.f) ? y : LEAK * y;
        o4[i] = v;
    }
}

// ---------------------------------------------------------------------------
extern "C" void kernel_launch(void* const* d_in, const int* in_sizes, int n_in,
                              void* d_out, int out_size)
{
    const float* feats = (const float*)d_in[0];
    const float* W     = (const float*)d_in[1];
    const float* bias  = (const float*)d_in[2];
    const float* gamma = (const float*)d_in[3];
    const float* beta  = (const float*)d_in[4];
    const int*   neigh = (const int*)  d_in[5];
    float* out = (float*)d_out;

    const int N = in_sizes[0] / CIN;
    const int mblocks = (N + BM - 1) / BM;

    conv_kernel  <<<mblocks, 128>>>(feats, W, bias, neigh, out, N);
    stats_partial<<<STATS_BLOCKS, COUT>>>(out, N);
    stats_final  <<<1, COUT>>>(gamma, beta, N);
    bn_lrelu     <<<2048, 256>>>(out, N);
}

// round 11
// speedup vs baseline: 1.5588x; 1.0008x over previous
#include <cuda_runtime.h>

// SparseBlock: submanifold sparse conv (9-tap gathered GEMM) + BatchNorm(train) + LeakyReLU(0.333)
// Inputs (metadata order): feats [N,128] f32, W [9,128,128] f32, bias[128], gamma[128], beta[128],
//                          neigh_idx [N,9] int32 (sentinel value == N -> zero row)
// Output: [N,128] f32.

#define CIN   128
#define COUT  128
#define KTAPS 9
#define BM    64
#define BK    32
#define STATS_BLOCKS 1024
#define EPS_BN  1e-4f
#define LEAK    0.333f

typedef unsigned long long u64;

__device__ __forceinline__ u64 pack2(float lo, float hi) {
    u64 r;
    asm("mov.b64 %0, {%1, %2};" : "=l"(r) : "f"(lo), "f"(hi));
    return r;
}
__device__ __forceinline__ float2 unpack2(u64 v) {
    float2 r;
    asm("mov.b64 {%0, %1}, %2;" : "=f"(r.x), "=f"(r.y) : "l"(v));
    return r;
}
// Packed dual-FMA: d.lo += a.lo*b.lo ; d.hi += a.hi*b.hi  (FFMA2 — only reachable via PTX)
__device__ __forceinline__ void fma2(u64& d, u64 a, u64 b) {
    asm("fma.rn.f32x2 %0, %1, %2, %0;" : "+l"(d) : "l"(a), "l"(b));
}

// Deterministic-reduction scratch (no device-side allocation allowed).
__device__ float g_psum[STATS_BLOCKS * COUT];
__device__ float g_psumsq[STATS_BLOCKS * COUT];
__device__ float g_scale[COUT];
__device__ float g_shift[COUT];

// ---------------------------------------------------------------------------
// Phase A: gathered GEMM.  Tile: 64 rows x 128 cols, K = 9*128 (taps x Cin).
// 128 threads, each computing an 8x(4+4) micro-tile held as packed f32x2 pairs.
// ---------------------------------------------------------------------------
__global__ __launch_bounds__(128, 3)
void conv_kernel(const float* __restrict__ feats, const float* __restrict__ W,
                 const float* __restrict__ bias, const int* __restrict__ neigh,
                 float* __restrict__ out, int N)
{
    // As padded to 36 floats/row: 16B-aligned rows, conflict-free float4 stores.
    __shared__ __align__(16) float As[BM][36];
    __shared__ __align__(16) float Bs[BK][COUT];
    __shared__ int sNeigh[BM];

    const int t  = threadIdx.x;
    const int tr = t >> 4;          // 0..7  -> row group
    const int tc = t & 15;          // 0..15 -> col group
    const int r0 = tr * 8;
    const int c0 = tc * 4;          // first 4-col slab
    const int c1 = 64 + tc * 4;     // second 4-col slab (split avoids LDS conflicts)
    const int m0 = blockIdx.x * BM;

    u64 acc[8][4];
    {
        float4 b0 = *(const float4*)(bias + c0);
        float4 b1 = *(const float4*)(bias + c1);
        u64 i0 = pack2(b0.x, b0.y), i1 = pack2(b0.z, b0.w);
        u64 i2 = pack2(b1.x, b1.y), i3 = pack2(b1.z, b1.w);
        #pragma unroll
        for (int r = 0; r < 8; ++r) {
            acc[r][0] = i0; acc[r][1] = i1; acc[r][2] = i2; acc[r][3] = i3;
        }
    }

    for (int k = 0; k < KTAPS; ++k) {
        __syncthreads();                       // previous chunk's compute done
        if (t < BM) {
            int gr = m0 + t;
            sNeigh[t] = (gr < N) ? neigh[gr * KTAPS + k] : N;
        }
        __syncthreads();

        #pragma unroll
        for (int kc = 0; kc < CIN / BK; ++kc) {
            // ---- gather A chunk: 64 rows x 32 floats (float4 granularity) ----
            #pragma unroll
            for (int i = 0; i < 4; ++i) {
                int idx  = t + i * 128;        // 0..511
                int row  = idx >> 3;
                int quad = idx & 7;
                int nb   = sNeigh[row];
                float4 v = make_float4(0.f, 0.f, 0.f, 0.f);
                if (nb < N)
                    v = *(const float4*)(feats + (size_t)nb * CIN + kc * BK + quad * 4);
                *(float4*)(&As[row][quad * 4]) = v;
            }
            // ---- stage B chunk: W[k][kc*32 .. +32][0..128] ----
            const float* Wk = W + ((size_t)k * CIN + kc * BK) * COUT;
            #pragma unroll
            for (int i = 0; i < 8; ++i) {
                int idx = t + i * 128;         // 0..1023
                int row = idx >> 5;
                int q   = idx & 31;
                *(float4*)(&Bs[row][q * 4]) = *(const float4*)(Wk + row * COUT + q * 4);
            }
            __syncthreads();

            // ---- 32 k-steps, a-operand vectorized 4 at a time ----
            #pragma unroll
            for (int kk4 = 0; kk4 < BK; kk4 += 4) {
                float4 av[8];
                #pragma unroll
                for (int r = 0; r < 8; ++r)
                    av[r] = *(const float4*)(&As[r0 + r][kk4]);
                #pragma unroll
                for (int j = 0; j < 4; ++j) {
                    float4 b0 = *(const float4*)(&Bs[kk4 + j][c0]);
                    float4 b1 = *(const float4*)(&Bs[kk4 + j][c1]);
                    u64 bp0 = pack2(b0.x, b0.y), bp1 = pack2(b0.z, b0.w);
                    u64 bp2 = pack2(b1.x, b1.y), bp3 = pack2(b1.z, b1.w);
                    #pragma unroll
                    for (int r = 0; r < 8; ++r) {
                        float a = (j == 0) ? av[r].x : (j == 1) ? av[r].y
                                : (j == 2) ? av[r].z : av[r].w;
                        u64 aa = pack2(a, a);
                        fma2(acc[r][0], aa, bp0);
                        fma2(acc[r][1], aa, bp1);
                        fma2(acc[r][2], aa, bp2);
                        fma2(acc[r][3], aa, bp3);
                    }
                }
            }
            __syncthreads();
        }
    }

    // ---- epilogue: pre-BN conv output ----
    #pragma unroll
    for (int r = 0; r < 8; ++r) {
        int gr = m0 + r0 + r;
        if (gr < N) {
            float2 p0 = unpack2(acc[r][0]);
            float2 p1 = unpack2(acc[r][1]);
            float2 p2 = unpack2(acc[r][2]);
            float2 p3 = unpack2(acc[r][3]);
            *(float4*)(out + (size_t)gr * COUT + c0) = make_float4(p0.x, p0.y, p1.x, p1.y);
            *(float4*)(out + (size_t)gr * COUT + c1) = make_float4(p2.x, p2.y, p3.x, p3.y);
        }
    }
}

// ---------------------------------------------------------------------------
// Phase B1: per-block partial sums / sumsq per channel (deterministic order).
// ---------------------------------------------------------------------------
__global__ void stats_partial(const float* __restrict__ out, int N)
{
    const int c = threadIdx.x;                 // 128 threads = 128 channels
    float s = 0.f, s2 = 0.f;
    for (int r = blockIdx.x; r < N; r += gridDim.x) {
        float v = out[(size_t)r * COUT + c];
        s  += v;
        s2 += v * v;
    }
    g_psum  [blockIdx.x * COUT + c] = s;
    g_psumsq[blockIdx.x * COUT + c] = s2;
}

// ---------------------------------------------------------------------------
// Phase B2: final reduce -> scale/shift per channel.
// ---------------------------------------------------------------------------
__global__ void stats_final(const float* __restrict__ gamma,
                            const float* __restrict__ beta, int N)
{
    const int c = threadIdx.x;
    float s = 0.f, s2 = 0.f;
    for (int i = 0; i < STATS_BLOCKS; ++i) {
        s  += g_psum  [i * COUT + c];
        s2 += g_psumsq[i * COUT + c];
    }
    float invN = 1.f / (float)N;
    float mean = s * invN;
    float var  = s2 * invN - mean * mean;      // population variance (ddof=0)
    float rstd = rsqrtf(var + EPS_BN);
    float sc   = gamma[c] * rstd;
    g_scale[c] = sc;
    g_shift[c] = beta[c] - mean * sc;
}

// ---------------------------------------------------------------------------
// Phase C: in-place BN affine + LeakyReLU, float4 vectorized.
// ---------------------------------------------------------------------------
__global__ void bn_lrelu(float* __restrict__ out, int N)
{
    const size_t total4 = (size_t)N * (COUT / 4);
    float4* o4 = (float4*)out;
    for (size_t i = (size_t)blockIdx.x * blockDim.x + threadIdx.x;
         i < total4; i += (size_t)gridDim.x * blockDim.x) {
        float4 v = o4[i];
        int cb = (int)((i & (COUT / 4 - 1)) * 4);   // channel base, multiple of 4
        float4 sc = *(const float4*)(g_scale + cb);
        float4 sh = *(const float4*)(g_shift + cb);
        float y;
        y = v.x * sc.x + sh.x; v.x = (y > 0.f) ? y : LEAK * y;
        y = v.y * sc.y + sh.y; v.y = (y > 0.f) ? y : LEAK * y;
        y = v.z * sc.z + sh.z; v.z = (y > 0.f) ? y : LEAK * y;
        y = v.w * sc.w + sh.w; v.w = (y > 0.f) ? y : LEAK * y;
        o4[i] = v;
    }
}

// ---------------------------------------------------------------------------
extern "C" void kernel_launch(void* const* d_in, const int* in_sizes, int n_in,
                              void* d_out, int out_size)
{
    const float* feats = (const float*)d_in[0];
    const float* W     = (const float*)d_in[1];
    const float* bias  = (const float*)d_in[2];
    const float* gamma = (const float*)d_in[3];
    const float* beta  = (const float*)d_in[4];
    const int*   neigh = (const int*)  d_in[5];
    float* out = (float*)d_out;

    const int N = in_sizes[0] / CIN;
    const int mblocks = (N + BM - 1) / BM;

    conv_kernel  <<<mblocks, 128>>>(feats, W, bias, neigh, out, N);
    stats_partial<<<STATS_BLOCKS, COUT>>>(out, N);
    stats_final  <<<1, COUT>>>(gamma, beta, N);
    bn_lrelu     <<<2048, 256>>>(out, N);
}